// round 10
// baseline (speedup 1.0000x reference)
#include <cuda_runtime.h>

#define NN      256
#define DD      64
#define NH      4
#define DHD     32
#define NINNER  128
#define NOUT    516   // 384 qkv + 128 gate + 4 bias
#define ATT_SCALE 0.17677669529663687f  // 1/sqrt(32)

// ---------------- scratch (device globals: sanctioned, no runtime alloc) ----
__device__ float g_q   [NN*NH*NN*DHD];   // [n][h][c][d]
__device__ float g_k   [NN*NH*NN*DHD];
__device__ float g_v   [NN*NH*NN*DHD];
__device__ float g_gate[NN*NN*NINNER];   // [n][i][e], post-sigmoid
__device__ float g_bias[NH*NN*NN];       // [h][i][j]
__device__ float g_ao  [NN*NN*NINNER];   // attn-out * gate
__device__ int   g_flags[2];             // [0]=swap ln pair, [1]=mask mode (0=f32,1=i32,2=u8)

// ---------------- packed f32x2 helpers (FFMA2: 2 MACs per issue) ------------
typedef unsigned long long ull;

__device__ __forceinline__ void ffma2(ull& d, ull a, ull b) {
    asm volatile("fma.rn.f32x2 %0, %1, %2, %0;" : "+l"(d) : "l"(a), "l"(b));
}
__device__ __forceinline__ ull addf2(ull a, ull b) {
    ull r; asm("add.rn.f32x2 %0, %1, %2;" : "=l"(r) : "l"(a), "l"(b)); return r;
}
__device__ __forceinline__ ull pack2(float lo, float hi) {
    ull r; asm("mov.b64 %0, {%1, %2};" : "=l"(r) : "f"(lo), "f"(hi)); return r;
}
__device__ __forceinline__ float2 unpack2(ull v) {
    float2 r; asm("mov.b64 {%0, %1}, %2;" : "=f"(r.x), "=f"(r.y) : "l"(v)); return r;
}
__device__ __forceinline__ float hsum2(ull a) { float2 f = unpack2(a); return f.x + f.y; }

// ---------------- kernel 0: resolve input ambiguities on-device -------------
__global__ void detect_kernel(const float* __restrict__ lnA,
                              const float* __restrict__ lnB,
                              const unsigned int* __restrict__ mask_w)
{
    __shared__ int sA, sB, sFloat, sInt;
    if (threadIdx.x == 0) { sA = 1; sB = 1; sFloat = 1; sInt = 1; }
    __syncthreads();
    if (threadIdx.x < 64) {
        if (lnA[threadIdx.x] != 1.0f) atomicAnd(&sA, 0);
        if (lnB[threadIdx.x] != 1.0f) atomicAnd(&sB, 0);
    }
    for (int i = threadIdx.x; i < 4096; i += 256) {
        unsigned int w = mask_w[i];
        if (w != 0u && w != 0x3F800000u) atomicAnd(&sFloat, 0);
        if (w > 1u)                       atomicAnd(&sInt, 0);
    }
    __syncthreads();
    if (threadIdx.x == 0) {
        g_flags[0] = (!sA && sB) ? 1 : 0;
        g_flags[1] = sFloat ? 0 : (sInt ? 1 : 2);
    }
}

// ---------------- kernel 1: LN + QKV/gate/bias projection -------------------
// grid 128 blocks x 512 threads; thread = (row parity, column). 1 grid-row per
// thread: h stays in 32 ull regs; weights in smem read via LDS.128.
__global__ void __launch_bounds__(512, 1) prep_kernel(
    const float* __restrict__ z,
    const float* __restrict__ lnA, const float* __restrict__ lnB,
    const float* __restrict__ w_qkv, const float* __restrict__ w_bias,
    const float* __restrict__ w_gate)
{
    extern __shared__ float sm[];
    float* ws    = sm;                  // [NOUT][64]
    float* s_lnw = ws + NOUT * DD;
    float* s_lnb = s_lnw + DD;
    const int tid = threadIdx.x;

    const int swap = g_flags[0];
    const float* lnw = swap ? lnB : lnA;
    const float* lnb = swap ? lnA : lnB;

    for (int idx = tid; idx < 384 * DD; idx += 512) ws[idx]            = w_qkv[idx];
    for (int idx = tid; idx < 128 * DD; idx += 512) ws[384 * DD + idx] = w_gate[idx];
    for (int idx = tid; idx <   4 * DD; idx += 512) ws[512 * DD + idx] = w_bias[idx];
    if (tid < DD) { s_lnw[tid] = lnw[tid]; s_lnb[tid] = lnb[tid]; }
    __syncthreads();

    const int r = blockIdx.x * 2 + (tid >> 8);
    const int c = tid & 255;

    ull h2[32];
    {
        const float4* zp = (const float4*)(z + ((size_t)r * NN + c) * DD);
        float s = 0.f, sq = 0.f;
        #pragma unroll
        for (int k = 0; k < 16; k++) {
            float4 t = zp[k];
            s  += (t.x + t.y) + (t.z + t.w);
            sq += (t.x * t.x + t.y * t.y) + (t.z * t.z + t.w * t.w);
        }
        float mu  = s * (1.f / 64.f);
        float var = sq * (1.f / 64.f) - mu * mu;
        float rs  = rsqrtf(fmaxf(var, 0.f) + 1e-5f);
        #pragma unroll
        for (int k = 0; k < 16; k++) {             // second pass: L1 hits
            float4 t = zp[k];
            float a0 = (t.x - mu) * rs * s_lnw[4*k  ] + s_lnb[4*k  ];
            float a1 = (t.y - mu) * rs * s_lnw[4*k+1] + s_lnb[4*k+1];
            float a2 = (t.z - mu) * rs * s_lnw[4*k+2] + s_lnb[4*k+2];
            float a3 = (t.w - mu) * rs * s_lnw[4*k+3] + s_lnb[4*k+3];
            h2[2*k]   = pack2(a0, a1);
            h2[2*k+1] = pack2(a2, a3);
        }
    }

    for (int o = 0; o < NOUT; o++) {
        const ulonglong2* wr = (const ulonglong2*)(ws + o * DD);  // 256B-aligned rows
        ull a0=0, a1=0, a2=0, a3=0;
        #pragma unroll
        for (int k = 0; k < 16; k++) {              // 16x LDS.128 = FULL 64-dim row
            ulonglong2 w2 = wr[k];                  // floats 4k..4k+3
            ffma2((k & 1) ? a2 : a0, h2[2*k],   w2.x);
            ffma2((k & 1) ? a3 : a1, h2[2*k+1], w2.y);
        }
        a0 = addf2(a0, a1); a2 = addf2(a2, a3);
        float ra = hsum2(addf2(a0, a2));

        if (o < 384) {
            int s   = o >> 7;          // 0=q 1=k 2=v
            int rem = o & 127;         // h*32 + d
            float* base = (s == 0) ? g_q : (s == 1) ? g_k : g_v;
            int hh = rem >> 5, d = rem & 31;
            base[(((r) * NH + hh) * NN + c) * DHD + d] = ra;
        } else if (o < 512) {
            int e = o - 384;
            g_gate[((size_t)r * NN + c) * NINNER + e] = 1.f / (1.f + __expf(-ra));
        } else {
            int hh = o - 512;
            g_bias[((size_t)hh * NN + r) * NN + c] = ra;
        }
    }
}

// ---------------- kernel 2: masked softmax attention + gate -----------------
// block = (n, head), 256 threads, thread i owns query row i. K/V rows read as
// LDS.128; q pre-scaled; f32x2 reduction tree. Fixed-max softmax (logits O(1)).
__global__ void __launch_bounds__(256, 2) attn_kernel(const void* __restrict__ maskp)
{
    extern __shared__ float sm[];
    float* ks   = sm;                  // [256][32]
    float* vs   = ks + NN * DHD;       // [256][32]
    float* madd = vs + NN * DHD;       // [256]
    const int n  = blockIdx.x, hh = blockIdx.y;
    const int tid = threadIdx.x;

    {
        const float4* kg = (const float4*)(g_k + (size_t)((n * NH + hh) * NN) * DHD);
        const float4* vg = (const float4*)(g_v + (size_t)((n * NH + hh) * NN) * DHD);
        float4* ks4 = (float4*)ks; float4* vs4 = (float4*)vs;
        #pragma unroll
        for (int t = 0; t < 8; t++) {
            ks4[tid + 256 * t] = kg[tid + 256 * t];
            vs4[tid + 256 * t] = vg[tid + 256 * t];
        }
        const int mode = g_flags[1];
        bool on;
        if (mode == 2)      on = ((const unsigned char*)maskp)[n * NN + tid] != 0;
        else if (mode == 1) on = ((const int*)maskp)[n * NN + tid] != 0;
        else                on = ((const float*)maskp)[n * NN + tid] != 0.f;
        madd[tid] = on ? 0.f : -1e30f;
    }
    __syncthreads();

    const int i = tid;
    ull q2[16];                                    // q * ATT_SCALE, packed
    {
        const float4* qg = (const float4*)(g_q + (size_t)((n * NH + hh) * NN + i) * DHD);
        #pragma unroll
        for (int k = 0; k < 8; k++) {
            float4 t = qg[k];
            q2[2*k]   = pack2(t.x * ATT_SCALE, t.y * ATT_SCALE);
            q2[2*k+1] = pack2(t.z * ATT_SCALE, t.w * ATT_SCALE);
        }
    }
    const float* brow = g_bias + (size_t)(hh * NN + i) * NN;

    ull acc[16];
    #pragma unroll
    for (int k = 0; k < 16; k++) acc[k] = 0ull;
    float ssum = 0.f;

    for (int j0 = 0; j0 < NN; j0 += 4) {
        float4 b4 = *(const float4*)(brow + j0);
        float4 m4 = *(const float4*)(madd + j0);
        float cb[4] = {b4.x + m4.x, b4.y + m4.y, b4.z + m4.z, b4.w + m4.w};
        #pragma unroll
        for (int jj = 0; jj < 4; jj++) {
            int j = j0 + jj;
            const ulonglong2* krow = (const ulonglong2*)(ks + j * DHD);  // LDS.128 b'cast
            ull d0=0, d1=0, d2=0, d3=0;
            #pragma unroll
            for (int k = 0; k < 4; k++) {
                ulonglong2 kA = krow[2*k], kB = krow[2*k+1];
                ffma2(d0, q2[4*k],   kA.x);
                ffma2(d1, q2[4*k+1], kA.y);
                ffma2(d2, q2[4*k+2], kB.x);
                ffma2(d3, q2[4*k+3], kB.y);
            }
            d0 = addf2(d0, d1); d2 = addf2(d2, d3);
            float s = hsum2(addf2(d0, d2)) + cb[jj];
            float p = __expf(s);
            ssum += p;
            ull p2 = pack2(p, p);
            const ulonglong2* vrow = (const ulonglong2*)(vs + j * DHD);
            #pragma unroll
            for (int k = 0; k < 8; k++) {
                ulonglong2 v2 = vrow[k];
                ffma2(acc[2*k],   p2, v2.x);
                ffma2(acc[2*k+1], p2, v2.y);
            }
        }
    }

    float inv = 1.f / ssum;
    const float2* grow = (const float2*)(g_gate + (size_t)(n * NN + i) * NINNER + hh * DHD);
    float2*       aop  = (float2*)      (g_ao   + (size_t)(n * NN + i) * NINNER + hh * DHD);
    #pragma unroll
    for (int k = 0; k < 16; k++) {
        float2 a = unpack2(acc[k]);
        float2 g = grow[k];
        float2 o; o.x = a.x * inv * g.x; o.y = a.y * inv * g.y;
        aop[k] = o;
    }
}

// ---------------- kernel 3: (attn_out * gate) @ w_out^T ---------------------
// Register-tiled GEMM. Block = 128 positions, 8 warps; warp owns 8 outputs,
// lane owns 4 positions. Transposed smem: ws_t[e][64], us_t[e][132 pad].
// Per e: 1 LDS.128 (u, lane-contig) + 2 LDS.128 (ws, b'cast) + 16 FFMA2 = 32 MACs.
#define OUT_P   128
#define US_LD   132   // pad: row stride, keeps 16B alignment (132*4 % 16 == 0)
__global__ void __launch_bounds__(256, 2) out_kernel(
    const float* __restrict__ w_out, float* __restrict__ out)
{
    extern __shared__ float sm[];
    float* ws_t = sm;                    // [128 e][64 d]
    float* us_t = ws_t + NINNER * DD;    // [128 e][132]
    const int tid = threadIdx.x;

    for (int idx = tid; idx < DD * NINNER; idx += 256) {
        int d = idx >> 7, e = idx & 127;
        ws_t[e * DD + d] = w_out[idx];                 // transpose store
    }
    const int p0 = blockIdx.x * OUT_P;
    for (int idx = tid; idx < OUT_P * NINNER / 4; idx += 256) {
        int p = idx >> 5, e0 = (idx & 31) * 4;         // float4 over e
        float4 a = *(const float4*)(g_ao + (size_t)(p0 + p) * NINNER + e0);
        us_t[(e0    ) * US_LD + p] = a.x;
        us_t[(e0 + 1) * US_LD + p] = a.y;
        us_t[(e0 + 2) * US_LD + p] = a.z;
        us_t[(e0 + 3) * US_LD + p] = a.w;
    }
    __syncthreads();

    const int warp = tid >> 5, lane = tid & 31;
    const int obase = warp * 8;                        // 8 outputs per warp
    const int pl = lane * 4;                           // 4 positions per lane
    ull acc[4][4];                                     // [pos][o-pair]
    #pragma unroll
    for (int p = 0; p < 4; p++)
        #pragma unroll
        for (int q = 0; q < 4; q++) acc[p][q] = 0ull;

    #pragma unroll 4
    for (int e = 0; e < NINNER; e++) {
        float4 u4 = *(const float4*)(us_t + e * US_LD + pl);          // lane-contig
        const ulonglong2* wr = (const ulonglong2*)(ws_t + e * DD + obase);
        ulonglong2 wA = wr[0], wB = wr[1];                            // broadcast
        float uu[4] = {u4.x, u4.y, u4.z, u4.w};
        #pragma unroll
        for (int p = 0; p < 4; p++) {
            ull up = pack2(uu[p], uu[p]);
            ffma2(acc[p][0], up, wA.x);
            ffma2(acc[p][1], up, wA.y);
            ffma2(acc[p][2], up, wB.x);
            ffma2(acc[p][3], up, wB.y);
        }
    }

    #pragma unroll
    for (int p = 0; p < 4; p++) {
        float2 c0 = unpack2(acc[p][0]), c1 = unpack2(acc[p][1]);
        float2 c2 = unpack2(acc[p][2]), c3 = unpack2(acc[p][3]);
        float* op = out + (size_t)(p0 + pl + p) * DD + obase;
        float4 f0 = {c0.x, c0.y, c1.x, c1.y};
        float4 f1 = {c2.x, c2.y, c3.x, c3.y};
        *(float4*)op       = f0;
        *(float4*)(op + 4) = f1;
    }
}

// ---------------- launch -----------------------------------------------------
extern "C" void kernel_launch(void* const* d_in, const int* in_sizes, int n_in,
                              void* d_out, int out_size)
{
    // Resolve inputs by ELEMENT count:
    //   z=4194304 (or 16777216 if bytes), mask=65536, w_qkv=24576, w_bias=256
    // Tie pairs: {ln_w, ln_b} both 64; {w_out, w_gate} both 8192.
    // Ordering scheme inferred from z's index (0 -> insertion order, else
    // alphabetical); ln pair additionally verified on-device (ln_w all-ones).
    const float* z = 0; const void* maskp = 0;
    const float *w_qkv = 0, *w_bias = 0;
    int idx_z = -1, i64[2] = {-1, -1}, n64 = 0, i8k[2] = {-1, -1}, n8k = 0;
    for (int i = 0; i < n_in; i++) {
        int s = in_sizes[i];
        if      (s == 4194304 || s == 16777216) { z = (const float*)d_in[i]; idx_z = i; }
        else if (s == 65536)    { maskp = d_in[i]; }
        else if (s == 24576)    { w_qkv = (const float*)d_in[i]; }
        else if (s == 256)      { w_bias = (const float*)d_in[i]; }
        else if (s == 64   && n64 < 2) { i64[n64++] = i; }
        else if (s == 8192 && n8k < 2) { i8k[n8k++] = i; }
    }
    const bool alpha = (idx_z != 0);
    const float* lnA    = (const float*)d_in[alpha ? i64[1] : i64[0]];  // presumed ln_w
    const float* lnB    = (const float*)d_in[alpha ? i64[0] : i64[1]];  // presumed ln_b
    const float* w_out  = (const float*)d_in[alpha ? i8k[1] : i8k[0]];
    const float* w_gate = (const float*)d_in[alpha ? i8k[0] : i8k[1]];
    float* out = (float*)d_out;

    const int smem_prep = (NOUT * DD + 2 * DD) * 4;            // 132608 B
    const int smem_attn = (2 * NN * DHD + NN) * 4;             //  66560 B
    const int smem_out  = (NINNER * DD + NINNER * US_LD) * 4;  // 100352 B
    cudaFuncSetAttribute(prep_kernel, cudaFuncAttributeMaxDynamicSharedMemorySize, smem_prep);
    cudaFuncSetAttribute(attn_kernel, cudaFuncAttributeMaxDynamicSharedMemorySize, smem_attn);
    cudaFuncSetAttribute(out_kernel,  cudaFuncAttributeMaxDynamicSharedMemorySize, smem_out);

    detect_kernel<<<1, 256>>>(lnA, lnB, (const unsigned int*)maskp);
    prep_kernel<<<128, 512, smem_prep>>>(z, lnA, lnB, w_qkv, w_bias, w_gate);
    attn_kernel<<<dim3(NN, NH), 256, smem_attn>>>(maskp);
    out_kernel<<<NN * NN / OUT_P, 256, smem_out>>>(w_out, out);
}

// round 13
// speedup vs baseline: 1.2682x; 1.2682x over previous
#include <cuda_runtime.h>

#define NN      256
#define DD      64
#define NH      4
#define DHD     32
#define NINNER  128
#define NOUT    516   // 384 qkv + 128 gate + 4 bias
#define ATT_SCALE 0.17677669529663687f  // 1/sqrt(32)

// ---------------- scratch (device globals: sanctioned, no runtime alloc) ----
__device__ float g_q   [NN*NH*NN*DHD];   // [n][h][c][d]
__device__ float g_k   [NN*NH*NN*DHD];
__device__ float g_v   [NN*NH*NN*DHD];
__device__ float g_gate[NN*NN*NINNER];   // [n][i][e], post-sigmoid
__device__ float g_bias[NH*NN*NN];       // [h][i][j]
__device__ float g_ao  [NN*NN*NINNER];   // attn-out * gate
__device__ int   g_flags[2];             // [0]=swap ln pair, [1]=mask mode (0=f32,1=i32,2=u8)

// ---------------- packed f32x2 helpers (FFMA2: 2 MACs per issue) ------------
typedef unsigned long long ull;

__device__ __forceinline__ void ffma2(ull& d, ull a, ull b) {
    asm volatile("fma.rn.f32x2 %0, %1, %2, %0;" : "+l"(d) : "l"(a), "l"(b));
}
__device__ __forceinline__ ull addf2(ull a, ull b) {
    ull r; asm("add.rn.f32x2 %0, %1, %2;" : "=l"(r) : "l"(a), "l"(b)); return r;
}
__device__ __forceinline__ ull pack2(float lo, float hi) {
    ull r; asm("mov.b64 %0, {%1, %2};" : "=l"(r) : "f"(lo), "f"(hi)); return r;
}
__device__ __forceinline__ float2 unpack2(ull v) {
    float2 r; asm("mov.b64 {%0, %1}, %2;" : "=f"(r.x), "=f"(r.y) : "l"(v)); return r;
}
__device__ __forceinline__ float hsum2(ull a) { float2 f = unpack2(a); return f.x + f.y; }

// ---------------- kernel 0: resolve input ambiguities on-device -------------
__global__ void detect_kernel(const float* __restrict__ lnA,
                              const float* __restrict__ lnB,
                              const unsigned int* __restrict__ mask_w)
{
    __shared__ int sA, sB, sFloat, sInt;
    if (threadIdx.x == 0) { sA = 1; sB = 1; sFloat = 1; sInt = 1; }
    __syncthreads();
    if (threadIdx.x < 64) {
        if (lnA[threadIdx.x] != 1.0f) atomicAnd(&sA, 0);
        if (lnB[threadIdx.x] != 1.0f) atomicAnd(&sB, 0);
    }
    for (int i = threadIdx.x; i < 4096; i += 256) {
        unsigned int w = mask_w[i];
        if (w != 0u && w != 0x3F800000u) atomicAnd(&sFloat, 0);
        if (w > 1u)                       atomicAnd(&sInt, 0);
    }
    __syncthreads();
    if (threadIdx.x == 0) {
        g_flags[0] = (!sA && sB) ? 1 : 0;
        g_flags[1] = sFloat ? 0 : (sInt ? 1 : 2);
    }
}

// ---------------- kernel 1: LN + QKV/gate/bias projection (R6-proven) -------
// grid 128 blocks (2 grid-rows each), 256 threads (one per column position).
// All 516x64 weights live in smem; h lives in registers (32 f32x2 per row).
__global__ void __launch_bounds__(256, 1) prep_kernel(
    const float* __restrict__ z,
    const float* __restrict__ lnA, const float* __restrict__ lnB,
    const float* __restrict__ w_qkv, const float* __restrict__ w_bias,
    const float* __restrict__ w_gate)
{
    extern __shared__ float sm[];
    float* ws    = sm;                  // [NOUT][64]
    float* s_lnw = ws + NOUT * DD;
    float* s_lnb = s_lnw + DD;
    const int tid = threadIdx.x;

    const int swap = g_flags[0];
    const float* lnw = swap ? lnB : lnA;
    const float* lnb = swap ? lnA : lnB;

    for (int idx = tid; idx < 384 * DD; idx += 256) ws[idx]            = w_qkv[idx];
    for (int idx = tid; idx < 128 * DD; idx += 256) ws[384 * DD + idx] = w_gate[idx];
    for (int idx = tid; idx <   4 * DD; idx += 256) ws[512 * DD + idx] = w_bias[idx];
    if (tid < DD) { s_lnw[tid] = lnw[tid]; s_lnb[tid] = lnb[tid]; }
    __syncthreads();

    const int r0 = blockIdx.x * 2;
    const int c  = tid;

    ull h2[2][32];
    #pragma unroll
    for (int p = 0; p < 2; p++) {
        const float4* zp = (const float4*)(z + ((size_t)(r0 + p) * NN + c) * DD);
        float s = 0.f, sq = 0.f;
        #pragma unroll
        for (int k = 0; k < 16; k++) {
            float4 t = zp[k];
            s  += (t.x + t.y) + (t.z + t.w);
            sq += (t.x * t.x + t.y * t.y) + (t.z * t.z + t.w * t.w);
        }
        float mu  = s * (1.f / 64.f);
        float var = sq * (1.f / 64.f) - mu * mu;
        float rs  = rsqrtf(fmaxf(var, 0.f) + 1e-5f);
        #pragma unroll
        for (int k = 0; k < 16; k++) {             // second pass: L1 hits
            float4 t = zp[k];
            float a0 = (t.x - mu) * rs * s_lnw[4*k  ] + s_lnb[4*k  ];
            float a1 = (t.y - mu) * rs * s_lnw[4*k+1] + s_lnb[4*k+1];
            float a2 = (t.z - mu) * rs * s_lnw[4*k+2] + s_lnb[4*k+2];
            float a3 = (t.w - mu) * rs * s_lnw[4*k+3] + s_lnb[4*k+3];
            h2[p][2*k]   = pack2(a0, a1);
            h2[p][2*k+1] = pack2(a2, a3);
        }
    }

    for (int o = 0; o < NOUT; o++) {
        const ull* wr = (const ull*)(ws + o * DD);
        ull a0=0,a1=0,a2=0,a3=0, b0=0,b1=0,b2=0,b3=0;
        #pragma unroll
        for (int k = 0; k < 32; k += 4) {
            ull w0 = wr[k], w1 = wr[k+1], w2 = wr[k+2], w3 = wr[k+3];
            ffma2(a0, h2[0][k],   w0);  ffma2(b0, h2[1][k],   w0);
            ffma2(a1, h2[0][k+1], w1);  ffma2(b1, h2[1][k+1], w1);
            ffma2(a2, h2[0][k+2], w2);  ffma2(b2, h2[1][k+2], w2);
            ffma2(a3, h2[0][k+3], w3);  ffma2(b3, h2[1][k+3], w3);
        }
        float ra = (hsum2(a0) + hsum2(a1)) + (hsum2(a2) + hsum2(a3));
        float rb = (hsum2(b0) + hsum2(b1)) + (hsum2(b2) + hsum2(b3));

        if (o < 384) {
            int s   = o >> 7;          // 0=q 1=k 2=v
            int rem = o & 127;         // h*32 + d
            float* base = (s == 0) ? g_q : (s == 1) ? g_k : g_v;
            int hh = rem >> 5, d = rem & 31;
            base[(((r0    ) * NH + hh) * NN + c) * DHD + d] = ra;
            base[(((r0 + 1) * NH + hh) * NN + c) * DHD + d] = rb;
        } else if (o < 512) {
            int e = o - 384;
            g_gate[((size_t)(r0    ) * NN + c) * NINNER + e] = 1.f / (1.f + __expf(-ra));
            g_gate[((size_t)(r0 + 1) * NN + c) * NINNER + e] = 1.f / (1.f + __expf(-rb));
        } else {
            int hh = o - 512;
            g_bias[((size_t)hh * NN + r0    ) * NN + c] = ra;
            g_bias[((size_t)hh * NN + r0 + 1) * NN + c] = rb;
        }
    }
}

// ---------------- kernel 2: masked softmax attention + gate (QI=2) ----------
// block = (n, head), 128 threads; thread owns query rows tid and tid+128.
// One K/V row LDS feeds TWO dot/acc chains: per j = 32 LDS.64 + 64 FFMA2
// (1:2 ratio -> FFMA2-bound). Fixed-max softmax (logits O(1)).
__global__ void __launch_bounds__(128, 2) attn_kernel(const void* __restrict__ maskp)
{
    extern __shared__ float sm[];
    float* ks   = sm;                  // [256][32]
    float* vs   = ks + NN * DHD;       // [256][32]
    float* madd = vs + NN * DHD;       // [256]
    const int n  = blockIdx.x, hh = blockIdx.y;
    const int tid = threadIdx.x;

    {
        const float4* kg = (const float4*)(g_k + (size_t)((n * NH + hh) * NN) * DHD);
        const float4* vg = (const float4*)(g_v + (size_t)((n * NH + hh) * NN) * DHD);
        float4* ks4 = (float4*)ks; float4* vs4 = (float4*)vs;
        #pragma unroll
        for (int t = 0; t < 16; t++) {
            ks4[tid + 128 * t] = kg[tid + 128 * t];
            vs4[tid + 128 * t] = vg[tid + 128 * t];
        }
        const int mode = g_flags[1];
        #pragma unroll
        for (int p = 0; p < 2; p++) {
            int j = tid + 128 * p;
            bool on;
            if (mode == 2)      on = ((const unsigned char*)maskp)[n * NN + j] != 0;
            else if (mode == 1) on = ((const int*)maskp)[n * NN + j] != 0;
            else                on = ((const float*)maskp)[n * NN + j] != 0.f;
            madd[j] = on ? 0.f : -1e30f;
        }
    }
    __syncthreads();

    const int i0 = tid, i1 = tid + 128;
    ull q0[16], q1[16];                            // q * ATT_SCALE, packed
    {
        const float4* qg0 = (const float4*)(g_q + (size_t)((n * NH + hh) * NN + i0) * DHD);
        const float4* qg1 = (const float4*)(g_q + (size_t)((n * NH + hh) * NN + i1) * DHD);
        #pragma unroll
        for (int k = 0; k < 8; k++) {
            float4 t0 = qg0[k], t1 = qg1[k];
            q0[2*k]   = pack2(t0.x * ATT_SCALE, t0.y * ATT_SCALE);
            q0[2*k+1] = pack2(t0.z * ATT_SCALE, t0.w * ATT_SCALE);
            q1[2*k]   = pack2(t1.x * ATT_SCALE, t1.y * ATT_SCALE);
            q1[2*k+1] = pack2(t1.z * ATT_SCALE, t1.w * ATT_SCALE);
        }
    }
    const float* b0row = g_bias + (size_t)(hh * NN + i0) * NN;
    const float* b1row = g_bias + (size_t)(hh * NN + i1) * NN;

    ull acc0[16], acc1[16];
    #pragma unroll
    for (int k = 0; k < 16; k++) { acc0[k] = 0ull; acc1[k] = 0ull; }
    float ssum0 = 0.f, ssum1 = 0.f;

    for (int j0 = 0; j0 < NN; j0 += 4) {
        float4 bA = *(const float4*)(b0row + j0);
        float4 bB = *(const float4*)(b1row + j0);
        float4 m4 = *(const float4*)(madd + j0);
        float cb0[4] = {bA.x + m4.x, bA.y + m4.y, bA.z + m4.z, bA.w + m4.w};
        float cb1[4] = {bB.x + m4.x, bB.y + m4.y, bB.z + m4.z, bB.w + m4.w};
        #pragma unroll
        for (int jj = 0; jj < 4; jj++) {
            int j = j0 + jj;
            const ull* krow = (const ull*)(ks + j * DHD);   // broadcast LDS.64
            ull d00=0, d01=0, d02=0, d03=0;
            ull d10=0, d11=0, d12=0, d13=0;
            #pragma unroll
            for (int k = 0; k < 16; k += 4) {
                ull k0 = krow[k], k1 = krow[k+1], k2 = krow[k+2], k3 = krow[k+3];
                ffma2(d00, q0[k],   k0);  ffma2(d10, q1[k],   k0);
                ffma2(d01, q0[k+1], k1);  ffma2(d11, q1[k+1], k1);
                ffma2(d02, q0[k+2], k2);  ffma2(d12, q1[k+2], k2);
                ffma2(d03, q0[k+3], k3);  ffma2(d13, q1[k+3], k3);
            }
            d00 = addf2(d00, d01); d02 = addf2(d02, d03);
            d10 = addf2(d10, d11); d12 = addf2(d12, d13);
            float s0 = hsum2(addf2(d00, d02)) + cb0[jj];
            float s1 = hsum2(addf2(d10, d12)) + cb1[jj];
            float p0 = __expf(s0);
            float p1 = __expf(s1);
            ssum0 += p0;
            ssum1 += p1;
            ull p02 = pack2(p0, p0);
            ull p12 = pack2(p1, p1);
            const ull* vrow = (const ull*)(vs + j * DHD);   // broadcast LDS.64
            #pragma unroll
            for (int k = 0; k < 16; k++) {
                ull vv = vrow[k];
                ffma2(acc0[k], p02, vv);
                ffma2(acc1[k], p12, vv);
            }
        }
    }

    {
        float inv0 = 1.f / ssum0;
        float inv1 = 1.f / ssum1;
        const float2* g0 = (const float2*)(g_gate + (size_t)(n * NN + i0) * NINNER + hh * DHD);
        const float2* g1 = (const float2*)(g_gate + (size_t)(n * NN + i1) * NINNER + hh * DHD);
        float2* a0p = (float2*)(g_ao + (size_t)(n * NN + i0) * NINNER + hh * DHD);
        float2* a1p = (float2*)(g_ao + (size_t)(n * NN + i1) * NINNER + hh * DHD);
        #pragma unroll
        for (int k = 0; k < 16; k++) {
            float2 a = unpack2(acc0[k]); float2 g = g0[k];
            float2 o; o.x = a.x * inv0 * g.x; o.y = a.y * inv0 * g.y;
            a0p[k] = o;
            float2 b = unpack2(acc1[k]); float2 h = g1[k];
            float2 u; u.x = b.x * inv1 * h.x; u.y = b.y * inv1 * h.y;
            a1p[k] = u;
        }
    }
}

// ---------------- kernel 3: (attn_out * gate) @ w_out^T (R10-proven) --------
// Register-tiled GEMM. Block = 128 positions, 8 warps; warp owns 8 outputs,
// lane owns 4 positions. Transposed smem: ws_t[e][64], us_t[e][132 pad].
#define OUT_P   128
#define US_LD   132   // pad: row stride, keeps 16B alignment (132*4 % 16 == 0)
__global__ void __launch_bounds__(256, 2) out_kernel(
    const float* __restrict__ w_out, float* __restrict__ out)
{
    extern __shared__ float sm[];
    float* ws_t = sm;                    // [128 e][64 d]
    float* us_t = ws_t + NINNER * DD;    // [128 e][132]
    const int tid = threadIdx.x;

    for (int idx = tid; idx < DD * NINNER; idx += 256) {
        int d = idx >> 7, e = idx & 127;
        ws_t[e * DD + d] = w_out[idx];                 // transpose store
    }
    const int p0 = blockIdx.x * OUT_P;
    for (int idx = tid; idx < OUT_P * NINNER / 4; idx += 256) {
        int p = idx >> 5, e0 = (idx & 31) * 4;         // float4 over e
        float4 a = *(const float4*)(g_ao + (size_t)(p0 + p) * NINNER + e0);
        us_t[(e0    ) * US_LD + p] = a.x;
        us_t[(e0 + 1) * US_LD + p] = a.y;
        us_t[(e0 + 2) * US_LD + p] = a.z;
        us_t[(e0 + 3) * US_LD + p] = a.w;
    }
    __syncthreads();

    const int warp = tid >> 5, lane = tid & 31;
    const int obase = warp * 8;                        // 8 outputs per warp
    const int pl = lane * 4;                           // 4 positions per lane
    ull acc[4][4];                                     // [pos][o-pair]
    #pragma unroll
    for (int p = 0; p < 4; p++)
        #pragma unroll
        for (int q = 0; q < 4; q++) acc[p][q] = 0ull;

    #pragma unroll 4
    for (int e = 0; e < NINNER; e++) {
        float4 u4 = *(const float4*)(us_t + e * US_LD + pl);          // lane-contig
        const ulonglong2* wr = (const ulonglong2*)(ws_t + e * DD + obase);
        ulonglong2 wA = wr[0], wB = wr[1];                            // broadcast
        float uu[4] = {u4.x, u4.y, u4.z, u4.w};
        #pragma unroll
        for (int p = 0; p < 4; p++) {
            ull up = pack2(uu[p], uu[p]);
            ffma2(acc[p][0], up, wA.x);
            ffma2(acc[p][1], up, wA.y);
            ffma2(acc[p][2], up, wB.x);
            ffma2(acc[p][3], up, wB.y);
        }
    }

    #pragma unroll
    for (int p = 0; p < 4; p++) {
        float2 c0 = unpack2(acc[p][0]), c1 = unpack2(acc[p][1]);
        float2 c2 = unpack2(acc[p][2]), c3 = unpack2(acc[p][3]);
        float* op = out + (size_t)(p0 + pl + p) * DD + obase;
        float4 f0 = {c0.x, c0.y, c1.x, c1.y};
        float4 f1 = {c2.x, c2.y, c3.x, c3.y};
        *(float4*)op       = f0;
        *(float4*)(op + 4) = f1;
    }
}

// ---------------- launch -----------------------------------------------------
extern "C" void kernel_launch(void* const* d_in, const int* in_sizes, int n_in,
                              void* d_out, int out_size)
{
    // Resolve inputs by ELEMENT count:
    //   z=4194304 (or 16777216 if bytes), mask=65536, w_qkv=24576, w_bias=256
    // Tie pairs: {ln_w, ln_b} both 64; {w_out, w_gate} both 8192.
    // Ordering scheme inferred from z's index (0 -> insertion order, else
    // alphabetical); ln pair additionally verified on-device (ln_w all-ones).
    const float* z = 0; const void* maskp = 0;
    const float *w_qkv = 0, *w_bias = 0;
    int idx_z = -1, i64[2] = {-1, -1}, n64 = 0, i8k[2] = {-1, -1}, n8k = 0;
    for (int i = 0; i < n_in; i++) {
        int s = in_sizes[i];
        if      (s == 4194304 || s == 16777216) { z = (const float*)d_in[i]; idx_z = i; }
        else if (s == 65536)    { maskp = d_in[i]; }
        else if (s == 24576)    { w_qkv = (const float*)d_in[i]; }
        else if (s == 256)      { w_bias = (const float*)d_in[i]; }
        else if (s == 64   && n64 < 2) { i64[n64++] = i; }
        else if (s == 8192 && n8k < 2) { i8k[n8k++] = i; }
    }
    const bool alpha = (idx_z != 0);
    const float* lnA    = (const float*)d_in[alpha ? i64[1] : i64[0]];  // presumed ln_w
    const float* lnB    = (const float*)d_in[alpha ? i64[0] : i64[1]];  // presumed ln_b
    const float* w_out  = (const float*)d_in[alpha ? i8k[1] : i8k[0]];
    const float* w_gate = (const float*)d_in[alpha ? i8k[0] : i8k[1]];
    float* out = (float*)d_out;

    const int smem_prep = (NOUT * DD + 2 * DD) * 4;            // 132608 B
    const int smem_attn = (2 * NN * DHD + NN) * 4;             //  66560 B
    const int smem_out  = (NINNER * DD + NINNER * US_LD) * 4;  // 100352 B
    cudaFuncSetAttribute(prep_kernel, cudaFuncAttributeMaxDynamicSharedMemorySize, smem_prep);
    cudaFuncSetAttribute(attn_kernel, cudaFuncAttributeMaxDynamicSharedMemorySize, smem_attn);
    cudaFuncSetAttribute(out_kernel,  cudaFuncAttributeMaxDynamicSharedMemorySize, smem_out);

    detect_kernel<<<1, 256>>>(lnA, lnB, (const unsigned int*)maskp);
    prep_kernel<<<128, 256, smem_prep>>>(z, lnA, lnB, w_qkv, w_bias, w_gate);
    attn_kernel<<<dim3(NN, NH), 128, smem_attn>>>(maskp);
    out_kernel<<<NN * NN / OUT_P, 256, smem_out>>>(w_out, out);
}